// round 8
// baseline (speedup 1.0000x reference)
#include <cuda_runtime.h>
#include <cstdint>

#define N_NODES 100000
#define N_EDGES 320000
#define N_GRAPHS 4096
#define HID 256
#define NFEAT 28

// ---------------- device scratch (zero-fill bss, no runtime alloc) ----------
__device__ float d_agg28[N_NODES * NFEAT];
__device__ float d_agg[N_NODES * HID];
__device__ float d_x1[N_NODES * HID];
__device__ float d_x2[N_NODES * HID];
__device__ float d_x3[N_NODES * HID];
__device__ float d_x4[N_NODES * HID];
__device__ float d_g[N_GRAPHS * 4 * HID];
__device__ float d_h1[N_GRAPHS * HID];
__device__ float d_h2[N_GRAPHS * HID];
__device__ float d_h3[N_GRAPHS * HID];

// ---------------- utility kernels -------------------------------------------
__global__ void zero_f4(float4* p, int n4) {
    int i = blockIdx.x * blockDim.x + threadIdx.x;
    if (i < n4) p[i] = make_float4(0.f, 0.f, 0.f, 0.f);
}

__device__ __forceinline__ void red_add_v4(float* p, float4 v) {
    asm volatile("red.global.add.v4.f32 [%0], {%1,%2,%3,%4};"
                 :: "l"(p), "f"(v.x), "f"(v.y), "f"(v.z), "f"(v.w)
                 : "memory");
}

// scatter-add x[src] (28 feats = 7 float4) into agg28[dst]; 8 threads/edge
__global__ void scatter28(const float* __restrict__ x,
                          const int* __restrict__ ei,
                          float* __restrict__ agg, int E) {
    int t = blockIdx.x * blockDim.x + threadIdx.x;
    int e = t >> 3;
    int c = t & 7;
    if (e >= E || c >= 7) return;
    int s = ei[e];
    int d = ei[E + e];
    float4 v = *(const float4*)(x + (size_t)s * NFEAT + c * 4);
    red_add_v4(agg + (size_t)d * NFEAT + c * 4, v);
}

// scatter-add x[src] (256 feats) into agg[dst]; 64 threads/edge, red.v4
__global__ void scatter256(const float* __restrict__ x,
                           const int* __restrict__ ei,
                           float* __restrict__ agg, int E) {
    int t = blockIdx.x * blockDim.x + threadIdx.x;
    int e = t >> 6;
    int c = (t & 63) << 2;
    if (e >= E) return;
    int s = ei[e];
    int d = ei[E + e];
    float4 v = *(const float4*)(x + (size_t)s * HID + c);
    red_add_v4(agg + (size_t)d * HID + c, v);
}

// layer 1: out = relu(agg28 @ W_rel^T + b + x @ W_root^T)  (K=28, NOUT=256)
__global__ __launch_bounds__(256)
void layer1_kernel(const float* __restrict__ agg28, const float* __restrict__ x,
                   const float* __restrict__ W_rel, const float* __restrict__ b,
                   const float* __restrict__ W_root, float* __restrict__ out, int M) {
    __shared__ float sa[16][NFEAT];
    __shared__ float sx[16][NFEAT];
    int r0 = blockIdx.x * 16;
    for (int i = threadIdx.x; i < 16 * NFEAT; i += 256) {
        int r = i / NFEAT, c = i % NFEAT;
        int row = r0 + r;
        sa[r][c] = (row < M) ? agg28[(size_t)row * NFEAT + c] : 0.f;
        sx[r][c] = (row < M) ? x[(size_t)row * NFEAT + c] : 0.f;
    }
    __syncthreads();
    int o = threadIdx.x;  // output column 0..255
    float wr[NFEAT], wo[NFEAT];
#pragma unroll
    for (int k = 0; k < NFEAT; k++) {
        wr[k] = W_rel[o * NFEAT + k];
        wo[k] = W_root[o * NFEAT + k];
    }
    float bo = b[o];
#pragma unroll 4
    for (int r = 0; r < 16; r++) {
        int row = r0 + r;
        if (row >= M) break;
        float acc = bo;
#pragma unroll
        for (int k = 0; k < NFEAT; k++) acc += sa[r][k] * wr[k] + sx[r][k] * wo[k];
        out[(size_t)row * HID + o] = fmaxf(acc, 0.f);
    }
}

// =================== tf32 tensor-core dual-segment NT GEMM ===================
// C[M,256] = relu?( bias + A0[M,K0] @ B0[256,K0]^T + A1[M,K1] @ B1[256,K1]^T )
// 128x128 CTA tile, BK=16, 3-stage cp.async pipeline, 8 warps (4M x 2N),
// warp tile 32x64, mma.sync.m16n8k8 tf32 with cvt.rna at fragment load.

#define GBM 128
#define GBN 128
#define GBK 16
#define SSTR 20     // smem row stride in floats
#define STAGES 3
#define STAGE_F ((GBM + GBN) * SSTR)              // floats per stage
#define GEMM_SMEM_BYTES (STAGES * STAGE_F * 4)    // 61440

__device__ __forceinline__ uint32_t f2tf32(float x) {
    uint32_t u;
    asm("cvt.rna.tf32.f32 %0, %1;" : "=r"(u) : "f"(x));
    return u;
}

__device__ __forceinline__ void cp_async16(uint32_t dst, const void* src, int nbytes) {
    asm volatile("cp.async.cg.shared.global [%0], [%1], 16, %2;"
                 :: "r"(dst), "l"(src), "r"(nbytes) : "memory");
}

__device__ __forceinline__ void mma_tf32(float* c, const uint32_t* a, const uint32_t* b) {
    asm volatile(
        "mma.sync.aligned.m16n8k8.row.col.f32.tf32.tf32.f32 "
        "{%0,%1,%2,%3}, {%4,%5,%6,%7}, {%8,%9}, {%0,%1,%2,%3};"
        : "+f"(c[0]), "+f"(c[1]), "+f"(c[2]), "+f"(c[3])
        : "r"(a[0]), "r"(a[1]), "r"(a[2]), "r"(a[3]), "r"(b[0]), "r"(b[1]));
}

__global__ __launch_bounds__(256, 2)
void gemm_tf32_dual(const float* __restrict__ A0, int lda0,
                    const float* __restrict__ B0, int ldb0, int K0,
                    const float* __restrict__ A1, int lda1,
                    const float* __restrict__ B1, int ldb1, int K1,
                    const float* __restrict__ bias, float* __restrict__ C,
                    int M, int ldc, int relu) {
    extern __shared__ float smem[];
    float* Asm = smem;                         // [STAGES][GBM*SSTR]
    float* Bsm = smem + STAGES * GBM * SSTR;   // [STAGES][GBN*SSTR]
    uint32_t As_base = (uint32_t)__cvta_generic_to_shared(Asm);
    uint32_t Bs_base = (uint32_t)__cvta_generic_to_shared(Bsm);

    int tid = threadIdx.x;
    int lane = tid & 31;
    int wid = tid >> 5;
    int wm = wid & 3;   // 0..3 -> 32-row slice
    int wn = wid >> 2;  // 0..1 -> 64-col slice
    int bm = blockIdx.y * GBM;
    int bn = blockIdx.x * GBN;

    float acc[2][8][4];
#pragma unroll
    for (int mt = 0; mt < 2; mt++)
#pragma unroll
        for (int nt = 0; nt < 8; nt++)
#pragma unroll
            for (int i = 0; i < 4; i++) acc[mt][nt][i] = 0.f;

    int nk0 = K0 / GBK;
    int nk = nk0 + K1 / GBK;

    // copy mapping: 256 threads cover 128 rows x 16 cols (64B/row) in 2 passes
    int lr = tid >> 2;            // 0..63
    int lc = (tid & 3) << 2;      // 0,4,8,12

    // issue cp.async for pipeline stage s into buffer buf
    auto issue_stage = [&](int s, int bufi) {
        const float* A; const float* B; int lda, ldb, ko;
        if (s < nk0) { A = A0; B = B0; lda = lda0; ldb = ldb0; ko = s * GBK; }
        else         { A = A1; B = B1; lda = lda1; ldb = ldb1; ko = (s - nk0) * GBK; }
#pragma unroll
        for (int j = 0; j < 2; j++) {
            int rr = lr + j * 64;
            int row = bm + rr;
            int okA = (row < M);
            const float* gA = A + (size_t)(okA ? row : 0) * lda + ko + lc;
            uint32_t da = As_base + (uint32_t)(bufi * (GBM * SSTR) + rr * SSTR + lc) * 4u;
            cp_async16(da, gA, okA ? 16 : 0);
            const float* gB = B + (size_t)(bn + rr) * ldb + ko + lc;
            uint32_t db = Bs_base + (uint32_t)(bufi * (GBN * SSTR) + rr * SSTR + lc) * 4u;
            cp_async16(db, gB, 16);
        }
        asm volatile("cp.async.commit_group;" ::: "memory");
    };

    // prologue: prefetch STAGES-1 stages
#pragma unroll
    for (int s = 0; s < STAGES - 1; s++) {
        if (s < nk) issue_stage(s, s);
        else asm volatile("cp.async.commit_group;" ::: "memory");
    }

    int grp = lane >> 2;  // 0..7
    int qid = lane & 3;   // 0..3
    int buf = 0;

    for (int it = 0; it < nk; ++it) {
        asm volatile("cp.async.wait_group %0;" :: "n"(STAGES - 2));
        __syncthreads();

        // prefetch stage it+STAGES-1 into the buffer consumed at it-1
        int nx = it + STAGES - 1;
        if (nx < nk) issue_stage(nx, (buf + STAGES - 1) % STAGES);
        else asm volatile("cp.async.commit_group;" ::: "memory");

        const float* Ab = Asm + buf * (GBM * SSTR);
        const float* Bb = Bsm + buf * (GBN * SSTR);
#pragma unroll
        for (int kk = 0; kk < GBK; kk += 8) {
            uint32_t af[2][4];
            uint32_t bfr[8][2];
#pragma unroll
            for (int mt = 0; mt < 2; mt++) {
                int r0 = wm * 32 + mt * 16 + grp;
                af[mt][0] = f2tf32(Ab[(r0    ) * SSTR + kk + qid]);
                af[mt][1] = f2tf32(Ab[(r0 + 8) * SSTR + kk + qid]);
                af[mt][2] = f2tf32(Ab[(r0    ) * SSTR + kk + qid + 4]);
                af[mt][3] = f2tf32(Ab[(r0 + 8) * SSTR + kk + qid + 4]);
            }
#pragma unroll
            for (int nt = 0; nt < 8; nt++) {
                int n0 = wn * 64 + nt * 8 + grp;
                bfr[nt][0] = f2tf32(Bb[n0 * SSTR + kk + qid]);
                bfr[nt][1] = f2tf32(Bb[n0 * SSTR + kk + qid + 4]);
            }
#pragma unroll
            for (int mt = 0; mt < 2; mt++)
#pragma unroll
                for (int nt = 0; nt < 8; nt++) mma_tf32(acc[mt][nt], af[mt], bfr[nt]);
        }
        buf = (buf + 1) % STAGES;
    }

    // ---- epilogue: bias + optional relu ----
#pragma unroll
    for (int mt = 0; mt < 2; mt++) {
#pragma unroll
        for (int nt = 0; nt < 8; nt++) {
            int row = bm + wm * 32 + mt * 16 + grp;
            int col = bn + wn * 64 + nt * 8 + 2 * qid;
            float b0 = bias[col], b1 = bias[col + 1];
            float2 v0, v1;
            v0.x = acc[mt][nt][0] + b0; v0.y = acc[mt][nt][1] + b1;
            v1.x = acc[mt][nt][2] + b0; v1.y = acc[mt][nt][3] + b1;
            if (relu) {
                v0.x = fmaxf(v0.x, 0.f); v0.y = fmaxf(v0.y, 0.f);
                v1.x = fmaxf(v1.x, 0.f); v1.y = fmaxf(v1.y, 0.f);
            }
            if (row < M)     *(float2*)(C + (size_t)row * ldc + col) = v0;
            if (row + 8 < M) *(float2*)(C + (size_t)(row + 8) * ldc + col) = v1;
        }
    }
}

// ------------- pooling: per-graph mean over concat(x1..x4) -------------------
__device__ __forceinline__ int lower_bound_i(const int* a, int n, int v) {
    int lo = 0, hi = n;
    while (lo < hi) {
        int mid = (lo + hi) >> 1;
        if (a[mid] < v) lo = mid + 1;
        else hi = mid;
    }
    return lo;
}

__global__ __launch_bounds__(256)
void pool_kernel(const float* __restrict__ x1, const float* __restrict__ x2,
                 const float* __restrict__ x3, const float* __restrict__ x4,
                 const int* __restrict__ batch, float* __restrict__ g, int N) {
    int gr = blockIdx.x;
    __shared__ int s_range[2];
    if (threadIdx.x == 0) {
        s_range[0] = lower_bound_i(batch, N, gr);
        s_range[1] = lower_bound_i(batch, N, gr + 1);
    }
    __syncthreads();
    int start = s_range[0], end = s_range[1];
    int tid = threadIdx.x;  // column 0..255
    float a0 = 0.f, a1 = 0.f, a2 = 0.f, a3 = 0.f;
    for (int n = start; n < end; n++) {
        size_t off = (size_t)n * HID + tid;
        a0 += x1[off];
        a1 += x2[off];
        a2 += x3[off];
        a3 += x4[off];
    }
    float inv = 1.f / fmaxf((float)(end - start), 1.f);
    size_t go = (size_t)gr * (4 * HID);
    g[go + 0 * HID + tid] = a0 * inv;
    g[go + 1 * HID + tid] = a1 * inv;
    g[go + 2 * HID + tid] = a2 * inv;
    g[go + 3 * HID + tid] = a3 * inv;
}

// ------------- final fc4: [G,256] @ w[256] + b -> [G] ------------------------
__global__ void fc4_kernel(const float* __restrict__ h, const float* __restrict__ w,
                           const float* __restrict__ b, float* __restrict__ out, int G) {
    int t = blockIdx.x * blockDim.x + threadIdx.x;
    int warp = t >> 5;
    int lane = t & 31;
    if (warp >= G) return;
    float acc = 0.f;
#pragma unroll
    for (int c = lane; c < HID; c += 32) acc += h[(size_t)warp * HID + c] * w[c];
#pragma unroll
    for (int off = 16; off; off >>= 1) acc += __shfl_xor_sync(0xFFFFFFFFu, acc, off);
    if (lane == 0) out[warp] = acc + b[0];
}

// ---------------- host orchestration ----------------------------------------
extern "C" void kernel_launch(void* const* d_in, const int* in_sizes, int n_in,
                              void* d_out, int out_size) {
    const float* x = (const float*)d_in[0];
    const int* ei = (const int*)d_in[1];       // int32 (JAX x64 disabled)
    const int* batch = (const int*)d_in[2];    // int32
    const float* W_rel[4] = {(const float*)d_in[3], (const float*)d_in[6],
                             (const float*)d_in[9], (const float*)d_in[12]};
    const float* b_rel[4] = {(const float*)d_in[4], (const float*)d_in[7],
                             (const float*)d_in[10], (const float*)d_in[13]};
    const float* W_root[4] = {(const float*)d_in[5], (const float*)d_in[8],
                              (const float*)d_in[11], (const float*)d_in[14]};
    const float* fc1_w = (const float*)d_in[15];
    const float* fc1_b = (const float*)d_in[16];
    const float* fc2_w = (const float*)d_in[17];
    const float* fc2_b = (const float*)d_in[18];
    const float* fc3_w = (const float*)d_in[19];
    const float* fc3_b = (const float*)d_in[20];
    const float* fc4_w = (const float*)d_in[21];
    const float* fc4_b = (const float*)d_in[22];
    float* out = (float*)d_out;

    int N = in_sizes[0] / NFEAT;   // 100000
    int E = in_sizes[1] / 2;       // 320000
    int G = out_size;              // 4096

    static float *agg28 = 0, *agg = 0, *x1 = 0, *x2 = 0, *x3 = 0, *x4 = 0,
                 *g = 0, *h1 = 0, *h2 = 0, *h3 = 0;
    if (!agg28) {
        cudaGetSymbolAddress((void**)&agg28, d_agg28);
        cudaGetSymbolAddress((void**)&agg, d_agg);
        cudaGetSymbolAddress((void**)&x1, d_x1);
        cudaGetSymbolAddress((void**)&x2, d_x2);
        cudaGetSymbolAddress((void**)&x3, d_x3);
        cudaGetSymbolAddress((void**)&x4, d_x4);
        cudaGetSymbolAddress((void**)&g, d_g);
        cudaGetSymbolAddress((void**)&h1, d_h1);
        cudaGetSymbolAddress((void**)&h2, d_h2);
        cudaGetSymbolAddress((void**)&h3, d_h3);
        cudaFuncSetAttribute(gemm_tf32_dual,
                             cudaFuncAttributeMaxDynamicSharedMemorySize,
                             GEMM_SMEM_BYTES);
    }

    float* xs[4] = {x1, x2, x3, x4};

    // ---- layer 1: scatter in 28-dim space, then tiny-K fused GEMM (fp32) ----
    {
        int n4 = N * NFEAT / 4;
        zero_f4<<<(n4 + 255) / 256, 256>>>((float4*)agg28, n4);
        int tot = E * 8;
        scatter28<<<(tot + 255) / 256, 256>>>(x, ei, agg28, E);
        layer1_kernel<<<(N + 15) / 16, 256>>>(agg28, x, W_rel[0], b_rel[0], W_root[0], x1, N);
    }

    // ---- layers 2..4 : scatter (red.v4) + tf32 dual GEMM (cp.async) ----
    for (int l = 1; l < 4; l++) {
        const float* xin = xs[l - 1];
        float* xout = xs[l];
        int n4 = N * HID / 4;
        zero_f4<<<(n4 + 255) / 256, 256>>>((float4*)agg, n4);
        int tot = E * 64;
        scatter256<<<(tot + 255) / 256, 256>>>(xin, ei, agg, E);
        dim3 grid(HID / GBN, (N + GBM - 1) / GBM);
        gemm_tf32_dual<<<grid, 256, GEMM_SMEM_BYTES>>>(
            agg, HID, W_rel[l], HID, HID,
            xin, HID, W_root[l], HID, HID,
            b_rel[l], xout, N, HID, 1);
    }

    // ---- global mean pool ----
    pool_kernel<<<G, 256>>>(x1, x2, x3, x4, batch, g, N);

    // ---- MLP (tf32 for fc1..fc3, warp-reduce for fc4) ----
    {
        dim3 grid(HID / GBN, (G + GBM - 1) / GBM);
        gemm_tf32_dual<<<grid, 256, GEMM_SMEM_BYTES>>>(
            g, 4 * HID, fc1_w, 4 * HID, 4 * HID,
            (const float*)0, 0, (const float*)0, 0, 0,
            fc1_b, h1, G, HID, 1);
        gemm_tf32_dual<<<grid, 256, GEMM_SMEM_BYTES>>>(
            h1, HID, fc2_w, HID, HID,
            (const float*)0, 0, (const float*)0, 0, 0,
            fc2_b, h2, G, HID, 1);
        gemm_tf32_dual<<<grid, 256, GEMM_SMEM_BYTES>>>(
            h2, HID, fc3_w, HID, HID,
            (const float*)0, 0, (const float*)0, 0, 0,
            fc3_b, h3, G, HID, 1);
        int tot = G * 32;
        fc4_kernel<<<(tot + 255) / 256, 256>>>(h3, fc4_w, fc4_b, out, G);
    }
}

// round 9
// speedup vs baseline: 1.1812x; 1.1812x over previous
#include <cuda_runtime.h>
#include <cstdint>

#define N_NODES 100000
#define N_EDGES 320000
#define N_GRAPHS 4096
#define HID 256
#define NFEAT 28

// ---------------- device scratch (zero-fill bss, no runtime alloc) ----------
__device__ float d_agg28[N_NODES * NFEAT];
__device__ float d_agg[N_NODES * HID];
__device__ float d_x1[N_NODES * HID];
__device__ float d_x2[N_NODES * HID];
__device__ float d_x3[N_NODES * HID];
__device__ float d_x4[N_NODES * HID];
__device__ float d_g[N_GRAPHS * 4 * HID];
__device__ float d_h1[N_GRAPHS * HID];
__device__ float d_h2[N_GRAPHS * HID];
__device__ float d_h3[N_GRAPHS * HID];

// CSR scratch
__device__ int d_deg[N_NODES];        // degree, then cursor
__device__ int d_rowptr[N_NODES + 1];
__device__ int d_csr[N_EDGES];
__device__ int d_bsum[256];
__device__ int d_boff[256];

// tf32-pre-rounded weights
__device__ float d_wr2[HID * HID], d_wo2[HID * HID];
__device__ float d_wr3[HID * HID], d_wo3[HID * HID];
__device__ float d_wr4[HID * HID], d_wo4[HID * HID];
__device__ float d_fc1w[HID * 4 * HID];
__device__ float d_fc2w[HID * HID];
__device__ float d_fc3w[HID * HID];

// ---------------- small utility kernels --------------------------------------
__global__ void zero_f4(float4* p, int n4) {
    int i = blockIdx.x * blockDim.x + threadIdx.x;
    if (i < n4) p[i] = make_float4(0.f, 0.f, 0.f, 0.f);
}

__global__ void zero_int(int* p, int n) {
    int i = blockIdx.x * blockDim.x + threadIdx.x;
    if (i < n) p[i] = 0;
}

__device__ __forceinline__ uint32_t f2tf32(float x) {
    uint32_t u;
    asm("cvt.rna.tf32.f32 %0, %1;" : "=r"(u) : "f"(x));
    return u;
}

__global__ void round_tf32_kernel(const float* __restrict__ in, float* __restrict__ outp, int n) {
    int i = blockIdx.x * blockDim.x + threadIdx.x;
    if (i < n) outp[i] = __uint_as_float(f2tf32(in[i]));
}

__device__ __forceinline__ void red_add_v4(float* p, float4 v) {
    asm volatile("red.global.add.v4.f32 [%0], {%1,%2,%3,%4};"
                 :: "l"(p), "f"(v.x), "f"(v.y), "f"(v.z), "f"(v.w)
                 : "memory");
}

// ---------------- CSR build ---------------------------------------------------
__global__ void hist_kernel(const int* __restrict__ ei, int* __restrict__ deg, int E) {
    int e = blockIdx.x * blockDim.x + threadIdx.x;
    if (e < E) atomicAdd(&deg[ei[E + e]], 1);
}

// inclusive scan of 512-chunks -> rowptr[i+1], block sums -> bsum
__global__ void scanA_kernel(const int* __restrict__ deg, int* __restrict__ rowptr,
                             int* __restrict__ bsum, int n) {
    __shared__ int s[512];
    int i = blockIdx.x * 512 + threadIdx.x;
    int v = (i < n) ? deg[i] : 0;
    s[threadIdx.x] = v;
    __syncthreads();
#pragma unroll
    for (int o = 1; o < 512; o <<= 1) {
        int t = (threadIdx.x >= o) ? s[threadIdx.x - o] : 0;
        __syncthreads();
        s[threadIdx.x] += t;
        __syncthreads();
    }
    if (i < n) rowptr[i + 1] = s[threadIdx.x];
    if (threadIdx.x == 511) bsum[blockIdx.x] = s[511];
}

// exclusive scan of block sums (nb <= 256), single block of 256
__global__ void scanB_kernel(const int* __restrict__ bsum, int* __restrict__ boff, int nb) {
    __shared__ int s[256];
    int v = (threadIdx.x < nb) ? bsum[threadIdx.x] : 0;
    s[threadIdx.x] = v;
    __syncthreads();
#pragma unroll
    for (int o = 1; o < 256; o <<= 1) {
        int t = (threadIdx.x >= o) ? s[threadIdx.x - o] : 0;
        __syncthreads();
        s[threadIdx.x] += t;
        __syncthreads();
    }
    if (threadIdx.x < nb) boff[threadIdx.x] = s[threadIdx.x] - v;
}

__global__ void scanC_kernel(int* __restrict__ rowptr, const int* __restrict__ boff, int n) {
    int i = blockIdx.x * blockDim.x + threadIdx.x;
    if (i == 0) rowptr[0] = 0;
    if (i < n) rowptr[i + 1] += boff[i >> 9];
}

__global__ void cursor_init_kernel(const int* __restrict__ rowptr, int* __restrict__ cursor, int n) {
    int i = blockIdx.x * blockDim.x + threadIdx.x;
    if (i < n) cursor[i] = rowptr[i];
}

__global__ void fill_csr_kernel(const int* __restrict__ ei, int* __restrict__ cursor,
                                int* __restrict__ csr, int E) {
    int e = blockIdx.x * blockDim.x + threadIdx.x;
    if (e >= E) return;
    int d = ei[E + e];
    int pos = atomicAdd(&cursor[d], 1);
    csr[pos] = ei[e];
}

// atomic-free aggregation: 64 threads per node, 4 nodes per block
__global__ __launch_bounds__(256)
void agg_csr_kernel(const float* __restrict__ x, const int* __restrict__ rowptr,
                    const int* __restrict__ csr, float* __restrict__ agg, int N) {
    int node = blockIdx.x * 4 + (threadIdx.x >> 6);
    int c = (threadIdx.x & 63) << 2;
    if (node >= N) return;
    int s0 = rowptr[node], s1 = rowptr[node + 1];
    float4 acc = make_float4(0.f, 0.f, 0.f, 0.f);
    for (int i = s0; i < s1; i++) {
        int src = __ldg(&csr[i]);
        float4 v = *(const float4*)(x + (size_t)src * HID + c);
        acc.x += v.x; acc.y += v.y; acc.z += v.z; acc.w += v.w;
    }
    *(float4*)(agg + (size_t)node * HID + c) = acc;
}

// ---------------- layer-1 path (K=28) ----------------------------------------
__global__ void scatter28(const float* __restrict__ x,
                          const int* __restrict__ ei,
                          float* __restrict__ agg, int E) {
    int t = blockIdx.x * blockDim.x + threadIdx.x;
    int e = t >> 3;
    int c = t & 7;
    if (e >= E || c >= 7) return;
    int s = ei[e];
    int d = ei[E + e];
    float4 v = *(const float4*)(x + (size_t)s * NFEAT + c * 4);
    red_add_v4(agg + (size_t)d * NFEAT + c * 4, v);
}

__global__ __launch_bounds__(256)
void layer1_kernel(const float* __restrict__ agg28, const float* __restrict__ x,
                   const float* __restrict__ W_rel, const float* __restrict__ b,
                   const float* __restrict__ W_root, float* __restrict__ out, int M) {
    __shared__ float sa[16][NFEAT];
    __shared__ float sx[16][NFEAT];
    int r0 = blockIdx.x * 16;
    for (int i = threadIdx.x; i < 16 * NFEAT; i += 256) {
        int r = i / NFEAT, c = i % NFEAT;
        int row = r0 + r;
        sa[r][c] = (row < M) ? agg28[(size_t)row * NFEAT + c] : 0.f;
        sx[r][c] = (row < M) ? x[(size_t)row * NFEAT + c] : 0.f;
    }
    __syncthreads();
    int o = threadIdx.x;
    float wr[NFEAT], wo[NFEAT];
#pragma unroll
    for (int k = 0; k < NFEAT; k++) {
        wr[k] = W_rel[o * NFEAT + k];
        wo[k] = W_root[o * NFEAT + k];
    }
    float bo = b[o];
#pragma unroll 4
    for (int r = 0; r < 16; r++) {
        int row = r0 + r;
        if (row >= M) break;
        float acc = bo;
#pragma unroll
        for (int k = 0; k < NFEAT; k++) acc += sa[r][k] * wr[k] + sx[r][k] * wo[k];
        out[(size_t)row * HID + o] = fmaxf(acc, 0.f);
    }
}

// =================== tf32 tensor-core dual-segment NT GEMM ===================
// B operands are pre-rounded tf32 (bit-cast); A converted with cvt.rna.
#define GBM 128
#define GBN 128
#define GBK 16
#define SSTR 20
#define STAGES 3
#define STAGE_F ((GBM + GBN) * SSTR)
#define GEMM_SMEM_BYTES (STAGES * STAGE_F * 4)

__device__ __forceinline__ void cp_async16(uint32_t dst, const void* src, int nbytes) {
    asm volatile("cp.async.cg.shared.global [%0], [%1], 16, %2;"
                 :: "r"(dst), "l"(src), "r"(nbytes) : "memory");
}

__device__ __forceinline__ void mma_tf32(float* c, const uint32_t* a, const uint32_t* b) {
    asm volatile(
        "mma.sync.aligned.m16n8k8.row.col.f32.tf32.tf32.f32 "
        "{%0,%1,%2,%3}, {%4,%5,%6,%7}, {%8,%9}, {%0,%1,%2,%3};"
        : "+f"(c[0]), "+f"(c[1]), "+f"(c[2]), "+f"(c[3])
        : "r"(a[0]), "r"(a[1]), "r"(a[2]), "r"(a[3]), "r"(b[0]), "r"(b[1]));
}

__global__ __launch_bounds__(256, 2)
void gemm_tf32_dual(const float* __restrict__ A0, int lda0,
                    const float* __restrict__ B0, int ldb0, int K0,
                    const float* __restrict__ A1, int lda1,
                    const float* __restrict__ B1, int ldb1, int K1,
                    const float* __restrict__ bias, float* __restrict__ C,
                    int M, int ldc, int relu) {
    extern __shared__ float smem[];
    float* Asm = smem;
    float* Bsm = smem + STAGES * GBM * SSTR;
    uint32_t As_base = (uint32_t)__cvta_generic_to_shared(Asm);
    uint32_t Bs_base = (uint32_t)__cvta_generic_to_shared(Bsm);

    int tid = threadIdx.x;
    int lane = tid & 31;
    int wid = tid >> 5;
    int wm = wid & 3;
    int wn = wid >> 2;
    int bm = blockIdx.y * GBM;
    int bn = blockIdx.x * GBN;

    float acc[2][8][4];
#pragma unroll
    for (int mt = 0; mt < 2; mt++)
#pragma unroll
        for (int nt = 0; nt < 8; nt++)
#pragma unroll
            for (int i = 0; i < 4; i++) acc[mt][nt][i] = 0.f;

    int nk0 = K0 / GBK;
    int nk = nk0 + K1 / GBK;

    int lr = tid >> 2;
    int lc = (tid & 3) << 2;

    auto issue_stage = [&](int s, int bufi) {
        const float* A; const float* B; int lda, ldb, ko;
        if (s < nk0) { A = A0; B = B0; lda = lda0; ldb = ldb0; ko = s * GBK; }
        else         { A = A1; B = B1; lda = lda1; ldb = ldb1; ko = (s - nk0) * GBK; }
#pragma unroll
        for (int j = 0; j < 2; j++) {
            int rr = lr + j * 64;
            int row = bm + rr;
            int okA = (row < M);
            const float* gA = A + (size_t)(okA ? row : 0) * lda + ko + lc;
            uint32_t da = As_base + (uint32_t)(bufi * (GBM * SSTR) + rr * SSTR + lc) * 4u;
            cp_async16(da, gA, okA ? 16 : 0);
            const float* gB = B + (size_t)(bn + rr) * ldb + ko + lc;
            uint32_t db = Bs_base + (uint32_t)(bufi * (GBN * SSTR) + rr * SSTR + lc) * 4u;
            cp_async16(db, gB, 16);
        }
        asm volatile("cp.async.commit_group;" ::: "memory");
    };

#pragma unroll
    for (int s = 0; s < STAGES - 1; s++) {
        if (s < nk) issue_stage(s, s);
        else asm volatile("cp.async.commit_group;" ::: "memory");
    }

    int grp = lane >> 2;
    int qid = lane & 3;
    int buf = 0;

    for (int it = 0; it < nk; ++it) {
        asm volatile("cp.async.wait_group %0;" :: "n"(STAGES - 2));
        __syncthreads();

        int nx = it + STAGES - 1;
        if (nx < nk) issue_stage(nx, (buf + STAGES - 1) % STAGES);
        else asm volatile("cp.async.commit_group;" ::: "memory");

        const float* Ab = Asm + buf * (GBM * SSTR);
        const float* Bb = Bsm + buf * (GBN * SSTR);
#pragma unroll
        for (int kk = 0; kk < GBK; kk += 8) {
            uint32_t af[2][4];
            uint32_t bfr[8][2];
#pragma unroll
            for (int mt = 0; mt < 2; mt++) {
                int r0 = wm * 32 + mt * 16 + grp;
                af[mt][0] = f2tf32(Ab[(r0    ) * SSTR + kk + qid]);
                af[mt][1] = f2tf32(Ab[(r0 + 8) * SSTR + kk + qid]);
                af[mt][2] = f2tf32(Ab[(r0    ) * SSTR + kk + qid + 4]);
                af[mt][3] = f2tf32(Ab[(r0 + 8) * SSTR + kk + qid + 4]);
            }
#pragma unroll
            for (int nt = 0; nt < 8; nt++) {
                int n0 = wn * 64 + nt * 8 + grp;
                bfr[nt][0] = __float_as_uint(Bb[n0 * SSTR + kk + qid]);      // pre-rounded
                bfr[nt][1] = __float_as_uint(Bb[n0 * SSTR + kk + qid + 4]);  // pre-rounded
            }
#pragma unroll
            for (int mt = 0; mt < 2; mt++)
#pragma unroll
                for (int nt = 0; nt < 8; nt++) mma_tf32(acc[mt][nt], af[mt], bfr[nt]);
        }
        buf = (buf + 1) % STAGES;
    }

#pragma unroll
    for (int mt = 0; mt < 2; mt++) {
#pragma unroll
        for (int nt = 0; nt < 8; nt++) {
            int row = bm + wm * 32 + mt * 16 + grp;
            int col = bn + wn * 64 + nt * 8 + 2 * qid;
            float b0 = bias[col], b1 = bias[col + 1];
            float2 v0, v1;
            v0.x = acc[mt][nt][0] + b0; v0.y = acc[mt][nt][1] + b1;
            v1.x = acc[mt][nt][2] + b0; v1.y = acc[mt][nt][3] + b1;
            if (relu) {
                v0.x = fmaxf(v0.x, 0.f); v0.y = fmaxf(v0.y, 0.f);
                v1.x = fmaxf(v1.x, 0.f); v1.y = fmaxf(v1.y, 0.f);
            }
            if (row < M)     *(float2*)(C + (size_t)row * ldc + col) = v0;
            if (row + 8 < M) *(float2*)(C + (size_t)(row + 8) * ldc + col) = v1;
        }
    }
}

// ------------- pooling -------------------------------------------------------
__device__ __forceinline__ int lower_bound_i(const int* a, int n, int v) {
    int lo = 0, hi = n;
    while (lo < hi) {
        int mid = (lo + hi) >> 1;
        if (a[mid] < v) lo = mid + 1;
        else hi = mid;
    }
    return lo;
}

__global__ __launch_bounds__(256)
void pool_kernel(const float* __restrict__ x1, const float* __restrict__ x2,
                 const float* __restrict__ x3, const float* __restrict__ x4,
                 const int* __restrict__ batch, float* __restrict__ g, int N) {
    int gr = blockIdx.x;
    __shared__ int s_range[2];
    if (threadIdx.x == 0) {
        s_range[0] = lower_bound_i(batch, N, gr);
        s_range[1] = lower_bound_i(batch, N, gr + 1);
    }
    __syncthreads();
    int start = s_range[0], end = s_range[1];
    int tid = threadIdx.x;
    float a0 = 0.f, a1 = 0.f, a2 = 0.f, a3 = 0.f;
    for (int n = start; n < end; n++) {
        size_t off = (size_t)n * HID + tid;
        a0 += x1[off];
        a1 += x2[off];
        a2 += x3[off];
        a3 += x4[off];
    }
    float inv = 1.f / fmaxf((float)(end - start), 1.f);
    size_t go = (size_t)gr * (4 * HID);
    g[go + 0 * HID + tid] = a0 * inv;
    g[go + 1 * HID + tid] = a1 * inv;
    g[go + 2 * HID + tid] = a2 * inv;
    g[go + 3 * HID + tid] = a3 * inv;
}

// ------------- final fc4 ------------------------------------------------------
__global__ void fc4_kernel(const float* __restrict__ h, const float* __restrict__ w,
                           const float* __restrict__ b, float* __restrict__ out, int G) {
    int t = blockIdx.x * blockDim.x + threadIdx.x;
    int warp = t >> 5;
    int lane = t & 31;
    if (warp >= G) return;
    float acc = 0.f;
#pragma unroll
    for (int c = lane; c < HID; c += 32) acc += h[(size_t)warp * HID + c] * w[c];
#pragma unroll
    for (int off = 16; off; off >>= 1) acc += __shfl_xor_sync(0xFFFFFFFFu, acc, off);
    if (lane == 0) out[warp] = acc + b[0];
}

// ---------------- host orchestration ----------------------------------------
extern "C" void kernel_launch(void* const* d_in, const int* in_sizes, int n_in,
                              void* d_out, int out_size) {
    const float* x = (const float*)d_in[0];
    const int* ei = (const int*)d_in[1];
    const int* batch = (const int*)d_in[2];
    const float* W_rel[4] = {(const float*)d_in[3], (const float*)d_in[6],
                             (const float*)d_in[9], (const float*)d_in[12]};
    const float* b_rel[4] = {(const float*)d_in[4], (const float*)d_in[7],
                             (const float*)d_in[10], (const float*)d_in[13]};
    const float* W_root[4] = {(const float*)d_in[5], (const float*)d_in[8],
                              (const float*)d_in[11], (const float*)d_in[14]};
    const float* fc1_w = (const float*)d_in[15];
    const float* fc1_b = (const float*)d_in[16];
    const float* fc2_w = (const float*)d_in[17];
    const float* fc2_b = (const float*)d_in[18];
    const float* fc3_w = (const float*)d_in[19];
    const float* fc3_b = (const float*)d_in[20];
    const float* fc4_w = (const float*)d_in[21];
    const float* fc4_b = (const float*)d_in[22];
    float* out = (float*)d_out;

    int N = in_sizes[0] / NFEAT;   // 100000
    int E = in_sizes[1] / 2;       // 320000
    int G = out_size;              // 4096

    static float *agg28 = 0, *agg = 0, *x1 = 0, *x2 = 0, *x3 = 0, *x4 = 0,
                 *g = 0, *h1 = 0, *h2 = 0, *h3 = 0;
    static float *wr[3], *wo[3], *fcw1, *fcw2, *fcw3;
    static int *deg = 0, *rowptr = 0, *csr = 0, *bsum = 0, *boff = 0;
    if (!agg28) {
        cudaGetSymbolAddress((void**)&agg28, d_agg28);
        cudaGetSymbolAddress((void**)&agg, d_agg);
        cudaGetSymbolAddress((void**)&x1, d_x1);
        cudaGetSymbolAddress((void**)&x2, d_x2);
        cudaGetSymbolAddress((void**)&x3, d_x3);
        cudaGetSymbolAddress((void**)&x4, d_x4);
        cudaGetSymbolAddress((void**)&g, d_g);
        cudaGetSymbolAddress((void**)&h1, d_h1);
        cudaGetSymbolAddress((void**)&h2, d_h2);
        cudaGetSymbolAddress((void**)&h3, d_h3);
        cudaGetSymbolAddress((void**)&wr[0], d_wr2);
        cudaGetSymbolAddress((void**)&wo[0], d_wo2);
        cudaGetSymbolAddress((void**)&wr[1], d_wr3);
        cudaGetSymbolAddress((void**)&wo[1], d_wo3);
        cudaGetSymbolAddress((void**)&wr[2], d_wr4);
        cudaGetSymbolAddress((void**)&wo[2], d_wo4);
        cudaGetSymbolAddress((void**)&fcw1, d_fc1w);
        cudaGetSymbolAddress((void**)&fcw2, d_fc2w);
        cudaGetSymbolAddress((void**)&fcw3, d_fc3w);
        cudaGetSymbolAddress((void**)&deg, d_deg);
        cudaGetSymbolAddress((void**)&rowptr, d_rowptr);
        cudaGetSymbolAddress((void**)&csr, d_csr);
        cudaGetSymbolAddress((void**)&bsum, d_bsum);
        cudaGetSymbolAddress((void**)&boff, d_boff);
        cudaFuncSetAttribute(gemm_tf32_dual,
                             cudaFuncAttributeMaxDynamicSharedMemorySize,
                             GEMM_SMEM_BYTES);
    }

    float* xs[4] = {x1, x2, x3, x4};

    // ---- pre-round weights to tf32 (B operands) ----
    {
        int n = HID * HID, blk = 256, gr2 = (n + blk - 1) / blk;
        for (int l = 0; l < 3; l++) {
            round_tf32_kernel<<<gr2, blk>>>(W_rel[l + 1], wr[l], n);
            round_tf32_kernel<<<gr2, blk>>>(W_root[l + 1], wo[l], n);
        }
        int n1 = HID * 4 * HID;
        round_tf32_kernel<<<(n1 + blk - 1) / blk, blk>>>(fc1_w, fcw1, n1);
        round_tf32_kernel<<<gr2, blk>>>(fc2_w, fcw2, n);
        round_tf32_kernel<<<gr2, blk>>>(fc3_w, fcw3, n);
    }

    // ---- build CSR (dst -> list of src) ----
    {
        zero_int<<<(N + 255) / 256, 256>>>(deg, N);
        hist_kernel<<<(E + 255) / 256, 256>>>(ei, deg, E);
        int nb = (N + 511) / 512;  // 196
        scanA_kernel<<<nb, 512>>>(deg, rowptr, bsum, N);
        scanB_kernel<<<1, 256>>>(bsum, boff, nb);
        scanC_kernel<<<(N + 255) / 256, 256>>>(rowptr, boff, N);
        cursor_init_kernel<<<(N + 255) / 256, 256>>>(rowptr, deg, N);  // deg = cursor
        fill_csr_kernel<<<(E + 255) / 256, 256>>>(ei, deg, csr, E);
    }

    // ---- layer 1: 28-dim scatter + tiny-K fused GEMM (fp32) ----
    {
        int n4 = N * NFEAT / 4;
        zero_f4<<<(n4 + 255) / 256, 256>>>((float4*)agg28, n4);
        int tot = E * 8;
        scatter28<<<(tot + 255) / 256, 256>>>(x, ei, agg28, E);
        layer1_kernel<<<(N + 15) / 16, 256>>>(agg28, x, W_rel[0], b_rel[0], W_root[0], x1, N);
    }

    // ---- layers 2..4 : CSR aggregation + tf32 dual GEMM ----
    for (int l = 1; l < 4; l++) {
        const float* xin = xs[l - 1];
        float* xout = xs[l];
        agg_csr_kernel<<<(N + 3) / 4, 256>>>(xin, rowptr, csr, agg, N);
        dim3 grid(HID / GBN, (N + GBM - 1) / GBM);
        gemm_tf32_dual<<<grid, 256, GEMM_SMEM_BYTES>>>(
            agg, HID, wr[l - 1], HID, HID,
            xin, HID, wo[l - 1], HID, HID,
            b_rel[l], xout, N, HID, 1);
    }

    // ---- global mean pool ----
    pool_kernel<<<G, 256>>>(x1, x2, x3, x4, batch, g, N);

    // ---- MLP ----
    {
        dim3 grid(HID / GBN, (G + GBM - 1) / GBM);
        gemm_tf32_dual<<<grid, 256, GEMM_SMEM_BYTES>>>(
            g, 4 * HID, fcw1, 4 * HID, 4 * HID,
            (const float*)0, 0, (const float*)0, 0, 0,
            fc1_b, h1, G, HID, 1);
        gemm_tf32_dual<<<grid, 256, GEMM_SMEM_BYTES>>>(
            h1, HID, fcw2, HID, HID,
            (const float*)0, 0, (const float*)0, 0, 0,
            fc2_b, h2, G, HID, 1);
        gemm_tf32_dual<<<grid, 256, GEMM_SMEM_BYTES>>>(
            h2, HID, fcw3, HID, HID,
            (const float*)0, 0, (const float*)0, 0, 0,
            fc3_b, h3, G, HID, 1);
        int tot = G * 32;
        fc4_kernel<<<(tot + 255) / 256, 256>>>(h3, fc4_w, fc4_b, out, G);
    }
}

// round 10
// speedup vs baseline: 1.2104x; 1.0248x over previous
#include <cuda_runtime.h>
#include <cstdint>

#define N_NODES 100000
#define N_EDGES 320000
#define N_GRAPHS 4096
#define HID 256
#define NFEAT 28

// ---------------- device scratch (zero-fill bss, no runtime alloc) ----------
__device__ float d_agg28[N_NODES * NFEAT];
__device__ float d_agg[N_NODES * HID];
__device__ float d_x1[N_NODES * HID];
__device__ float d_x2[N_NODES * HID];
__device__ float d_x3[N_NODES * HID];
__device__ float d_x4[N_NODES * HID];
__device__ float d_g[N_GRAPHS * 4 * HID];
__device__ float d_h1[N_GRAPHS * HID];
__device__ float d_h2[N_GRAPHS * HID];
__device__ float d_h3[N_GRAPHS * HID];

// CSR scratch
__device__ int d_deg[N_NODES];
__device__ int d_rowptr[N_NODES + 1];
__device__ int d_csr[N_EDGES];
__device__ int d_bsum[256];
__device__ int d_boff[256];

// tf32-pre-rounded weights
__device__ float d_wr2[HID * HID], d_wo2[HID * HID];
__device__ float d_wr3[HID * HID], d_wo3[HID * HID];
__device__ float d_wr4[HID * HID], d_wo4[HID * HID];
__device__ float d_fc1w[HID * 4 * HID];
__device__ float d_fc2w[HID * HID];
__device__ float d_fc3w[HID * HID];

// ---------------- small utility kernels --------------------------------------
__global__ void zero_f4(float4* p, int n4) {
    int i = blockIdx.x * blockDim.x + threadIdx.x;
    if (i < n4) p[i] = make_float4(0.f, 0.f, 0.f, 0.f);
}

__global__ void zero_int(int* p, int n) {
    int i = blockIdx.x * blockDim.x + threadIdx.x;
    if (i < n) p[i] = 0;
}

__device__ __forceinline__ uint32_t f2tf32(float x) {
    uint32_t u;
    asm("cvt.rna.tf32.f32 %0, %1;" : "=r"(u) : "f"(x));
    return u;
}

__device__ __forceinline__ float round_tf32(float x) {
    return __uint_as_float(f2tf32(x));
}

// merged weight rounding: 9 segments in one launch
struct WSeg { const float* src; float* dst; int n; };
struct WPack { WSeg seg[9]; };

__global__ void round_weights_kernel(WPack p, int total) {
    int i = blockIdx.x * blockDim.x + threadIdx.x;
    if (i >= total) return;
#pragma unroll
    for (int s = 0; s < 9; s++) {
        if (i < p.seg[s].n) {
            p.seg[s].dst[i] = round_tf32(p.seg[s].src[i]);
            return;
        }
        i -= p.seg[s].n;
    }
}

__device__ __forceinline__ void red_add_v4(float* p, float4 v) {
    asm volatile("red.global.add.v4.f32 [%0], {%1,%2,%3,%4};"
                 :: "l"(p), "f"(v.x), "f"(v.y), "f"(v.z), "f"(v.w)
                 : "memory");
}

// ---------------- CSR build ---------------------------------------------------
__global__ void hist_kernel(const int* __restrict__ ei, int* __restrict__ deg, int E) {
    int e = blockIdx.x * blockDim.x + threadIdx.x;
    if (e < E) atomicAdd(&deg[ei[E + e]], 1);
}

__global__ void scanA_kernel(const int* __restrict__ deg, int* __restrict__ rowptr,
                             int* __restrict__ bsum, int n) {
    __shared__ int s[512];
    int i = blockIdx.x * 512 + threadIdx.x;
    int v = (i < n) ? deg[i] : 0;
    s[threadIdx.x] = v;
    __syncthreads();
#pragma unroll
    for (int o = 1; o < 512; o <<= 1) {
        int t = (threadIdx.x >= o) ? s[threadIdx.x - o] : 0;
        __syncthreads();
        s[threadIdx.x] += t;
        __syncthreads();
    }
    if (i < n) rowptr[i + 1] = s[threadIdx.x];
    if (threadIdx.x == 511) bsum[blockIdx.x] = s[511];
}

__global__ void scanB_kernel(const int* __restrict__ bsum, int* __restrict__ boff, int nb) {
    __shared__ int s[256];
    int v = (threadIdx.x < nb) ? bsum[threadIdx.x] : 0;
    s[threadIdx.x] = v;
    __syncthreads();
#pragma unroll
    for (int o = 1; o < 256; o <<= 1) {
        int t = (threadIdx.x >= o) ? s[threadIdx.x - o] : 0;
        __syncthreads();
        s[threadIdx.x] += t;
        __syncthreads();
    }
    if (threadIdx.x < nb) boff[threadIdx.x] = s[threadIdx.x] - v;
}

__global__ void scanC_kernel(int* __restrict__ rowptr, const int* __restrict__ boff, int n) {
    int i = blockIdx.x * blockDim.x + threadIdx.x;
    if (i == 0) rowptr[0] = 0;
    if (i < n) rowptr[i + 1] += boff[i >> 9];
}

__global__ void cursor_init_kernel(const int* __restrict__ rowptr, int* __restrict__ cursor, int n) {
    int i = blockIdx.x * blockDim.x + threadIdx.x;
    if (i < n) cursor[i] = rowptr[i];
}

__global__ void fill_csr_kernel(const int* __restrict__ ei, int* __restrict__ cursor,
                                int* __restrict__ csr, int E) {
    int e = blockIdx.x * blockDim.x + threadIdx.x;
    if (e >= E) return;
    int d = ei[E + e];
    int pos = atomicAdd(&cursor[d], 1);
    csr[pos] = ei[e];
}

// atomic-free aggregation; writes tf32-rounded sums (A operand of GEMM)
__global__ __launch_bounds__(256)
void agg_csr_kernel(const float* __restrict__ x, const int* __restrict__ rowptr,
                    const int* __restrict__ csr, float* __restrict__ agg, int N) {
    int node = blockIdx.x * 4 + (threadIdx.x >> 6);
    int c = (threadIdx.x & 63) << 2;
    if (node >= N) return;
    int s0 = rowptr[node], s1 = rowptr[node + 1];
    float4 acc = make_float4(0.f, 0.f, 0.f, 0.f);
    for (int i = s0; i < s1; i++) {
        int src = __ldg(&csr[i]);
        float4 v = *(const float4*)(x + (size_t)src * HID + c);
        acc.x += v.x; acc.y += v.y; acc.z += v.z; acc.w += v.w;
    }
    acc.x = round_tf32(acc.x); acc.y = round_tf32(acc.y);
    acc.z = round_tf32(acc.z); acc.w = round_tf32(acc.w);
    *(float4*)(agg + (size_t)node * HID + c) = acc;
}

// ---------------- layer-1 path (K=28) ----------------------------------------
__global__ void scatter28(const float* __restrict__ x,
                          const int* __restrict__ ei,
                          float* __restrict__ agg, int E) {
    int t = blockIdx.x * blockDim.x + threadIdx.x;
    int e = t >> 3;
    int c = t & 7;
    if (e >= E || c >= 7) return;
    int s = ei[e];
    int d = ei[E + e];
    float4 v = *(const float4*)(x + (size_t)s * NFEAT + c * 4);
    red_add_v4(agg + (size_t)d * NFEAT + c * 4, v);
}

// output rounded to tf32 (x1 is an A operand of GEMM-2)
__global__ __launch_bounds__(256)
void layer1_kernel(const float* __restrict__ agg28, const float* __restrict__ x,
                   const float* __restrict__ W_rel, const float* __restrict__ b,
                   const float* __restrict__ W_root, float* __restrict__ out, int M) {
    __shared__ float sa[16][NFEAT];
    __shared__ float sx[16][NFEAT];
    int r0 = blockIdx.x * 16;
    for (int i = threadIdx.x; i < 16 * NFEAT; i += 256) {
        int r = i / NFEAT, c = i % NFEAT;
        int row = r0 + r;
        sa[r][c] = (row < M) ? agg28[(size_t)row * NFEAT + c] : 0.f;
        sx[r][c] = (row < M) ? x[(size_t)row * NFEAT + c] : 0.f;
    }
    __syncthreads();
    int o = threadIdx.x;
    float wr[NFEAT], wo[NFEAT];
#pragma unroll
    for (int k = 0; k < NFEAT; k++) {
        wr[k] = W_rel[o * NFEAT + k];
        wo[k] = W_root[o * NFEAT + k];
    }
    float bo = b[o];
#pragma unroll 4
    for (int r = 0; r < 16; r++) {
        int row = r0 + r;
        if (row >= M) break;
        float acc = bo;
#pragma unroll
        for (int k = 0; k < NFEAT; k++) acc += sa[r][k] * wr[k] + sx[r][k] * wo[k];
        out[(size_t)row * HID + o] = round_tf32(fmaxf(acc, 0.f));
    }
}

// =================== tf32 tensor-core dual-segment NT GEMM ===================
// CVT_A=false when A operands are pre-rounded tf32 (bit-cast fragments).
#define GBM 128
#define GBN 128
#define GBK 16
#define SSTR 20
#define STAGES 3
#define STAGE_F ((GBM + GBN) * SSTR)
#define GEMM_SMEM_BYTES (STAGES * STAGE_F * 4)

__device__ __forceinline__ void cp_async16(uint32_t dst, const void* src, int nbytes) {
    asm volatile("cp.async.cg.shared.global [%0], [%1], 16, %2;"
                 :: "r"(dst), "l"(src), "r"(nbytes) : "memory");
}

__device__ __forceinline__ void mma_tf32(float* c, const uint32_t* a, const uint32_t* b) {
    asm volatile(
        "mma.sync.aligned.m16n8k8.row.col.f32.tf32.tf32.f32 "
        "{%0,%1,%2,%3}, {%4,%5,%6,%7}, {%8,%9}, {%0,%1,%2,%3};"
        : "+f"(c[0]), "+f"(c[1]), "+f"(c[2]), "+f"(c[3])
        : "r"(a[0]), "r"(a[1]), "r"(a[2]), "r"(a[3]), "r"(b[0]), "r"(b[1]));
}

template <bool CVT_A>
__global__ __launch_bounds__(256, 2)
void gemm_tf32_dual(const float* __restrict__ A0, int lda0,
                    const float* __restrict__ B0, int ldb0, int K0,
                    const float* __restrict__ A1, int lda1,
                    const float* __restrict__ B1, int ldb1, int K1,
                    const float* __restrict__ bias, float* __restrict__ C,
                    int M, int ldc, int relu, int round_out) {
    extern __shared__ float smem[];
    float* Asm = smem;
    float* Bsm = smem + STAGES * GBM * SSTR;
    uint32_t As_base = (uint32_t)__cvta_generic_to_shared(Asm);
    uint32_t Bs_base = (uint32_t)__cvta_generic_to_shared(Bsm);

    int tid = threadIdx.x;
    int lane = tid & 31;
    int wid = tid >> 5;
    int wm = wid & 3;
    int wn = wid >> 2;
    int bm = blockIdx.y * GBM;
    int bn = blockIdx.x * GBN;

    float acc[2][8][4];
#pragma unroll
    for (int mt = 0; mt < 2; mt++)
#pragma unroll
        for (int nt = 0; nt < 8; nt++)
#pragma unroll
            for (int i = 0; i < 4; i++) acc[mt][nt][i] = 0.f;

    int nk0 = K0 / GBK;
    int nk = nk0 + K1 / GBK;

    int lr = tid >> 2;
    int lc = (tid & 3) << 2;

    auto issue_stage = [&](int s, int bufi) {
        const float* A; const float* B; int lda, ldb, ko;
        if (s < nk0) { A = A0; B = B0; lda = lda0; ldb = ldb0; ko = s * GBK; }
        else         { A = A1; B = B1; lda = lda1; ldb = ldb1; ko = (s - nk0) * GBK; }
#pragma unroll
        for (int j = 0; j < 2; j++) {
            int rr = lr + j * 64;
            int row = bm + rr;
            int okA = (row < M);
            const float* gA = A + (size_t)(okA ? row : 0) * lda + ko + lc;
            uint32_t da = As_base + (uint32_t)(bufi * (GBM * SSTR) + rr * SSTR + lc) * 4u;
            cp_async16(da, gA, okA ? 16 : 0);
            const float* gB = B + (size_t)(bn + rr) * ldb + ko + lc;
            uint32_t db = Bs_base + (uint32_t)(bufi * (GBN * SSTR) + rr * SSTR + lc) * 4u;
            cp_async16(db, gB, 16);
        }
        asm volatile("cp.async.commit_group;" ::: "memory");
    };

#pragma unroll
    for (int s = 0; s < STAGES - 1; s++) {
        if (s < nk) issue_stage(s, s);
        else asm volatile("cp.async.commit_group;" ::: "memory");
    }

    int grp = lane >> 2;
    int qid = lane & 3;
    int buf = 0;

    for (int it = 0; it < nk; ++it) {
        asm volatile("cp.async.wait_group %0;" :: "n"(STAGES - 2));
        __syncthreads();

        int nx = it + STAGES - 1;
        if (nx < nk) issue_stage(nx, (buf + STAGES - 1) % STAGES);
        else asm volatile("cp.async.commit_group;" ::: "memory");

        const float* Ab = Asm + buf * (GBM * SSTR);
        const float* Bb = Bsm + buf * (GBN * SSTR);
#pragma unroll
        for (int kk = 0; kk < GBK; kk += 8) {
            uint32_t af[2][4];
            uint32_t bfr[8][2];
#pragma unroll
            for (int mt = 0; mt < 2; mt++) {
                int r0 = wm * 32 + mt * 16 + grp;
                if (CVT_A) {
                    af[mt][0] = f2tf32(Ab[(r0    ) * SSTR + kk + qid]);
                    af[mt][1] = f2tf32(Ab[(r0 + 8) * SSTR + kk + qid]);
                    af[mt][2] = f2tf32(Ab[(r0    ) * SSTR + kk + qid + 4]);
                    af[mt][3] = f2tf32(Ab[(r0 + 8) * SSTR + kk + qid + 4]);
                } else {
                    af[mt][0] = __float_as_uint(Ab[(r0    ) * SSTR + kk + qid]);
                    af[mt][1] = __float_as_uint(Ab[(r0 + 8) * SSTR + kk + qid]);
                    af[mt][2] = __float_as_uint(Ab[(r0    ) * SSTR + kk + qid + 4]);
                    af[mt][3] = __float_as_uint(Ab[(r0 + 8) * SSTR + kk + qid + 4]);
                }
            }
#pragma unroll
            for (int nt = 0; nt < 8; nt++) {
                int n0 = wn * 64 + nt * 8 + grp;
                bfr[nt][0] = __float_as_uint(Bb[n0 * SSTR + kk + qid]);
                bfr[nt][1] = __float_as_uint(Bb[n0 * SSTR + kk + qid + 4]);
            }
#pragma unroll
            for (int mt = 0; mt < 2; mt++)
#pragma unroll
                for (int nt = 0; nt < 8; nt++) mma_tf32(acc[mt][nt], af[mt], bfr[nt]);
        }
        buf = (buf + 1) % STAGES;
    }

#pragma unroll
    for (int mt = 0; mt < 2; mt++) {
#pragma unroll
        for (int nt = 0; nt < 8; nt++) {
            int row = bm + wm * 32 + mt * 16 + grp;
            int col = bn + wn * 64 + nt * 8 + 2 * qid;
            float b0 = bias[col], b1 = bias[col + 1];
            float2 v0, v1;
            v0.x = acc[mt][nt][0] + b0; v0.y = acc[mt][nt][1] + b1;
            v1.x = acc[mt][nt][2] + b0; v1.y = acc[mt][nt][3] + b1;
            if (relu) {
                v0.x = fmaxf(v0.x, 0.f); v0.y = fmaxf(v0.y, 0.f);
                v1.x = fmaxf(v1.x, 0.f); v1.y = fmaxf(v1.y, 0.f);
            }
            if (round_out) {
                v0.x = round_tf32(v0.x); v0.y = round_tf32(v0.y);
                v1.x = round_tf32(v1.x); v1.y = round_tf32(v1.y);
            }
            if (row < M)     *(float2*)(C + (size_t)row * ldc + col) = v0;
            if (row + 8 < M) *(float2*)(C + (size_t)(row + 8) * ldc + col) = v1;
        }
    }
}

// ------------- pooling -------------------------------------------------------
__device__ __forceinline__ int lower_bound_i(const int* a, int n, int v) {
    int lo = 0, hi = n;
    while (lo < hi) {
        int mid = (lo + hi) >> 1;
        if (a[mid] < v) lo = mid + 1;
        else hi = mid;
    }
    return lo;
}

__global__ __launch_bounds__(256)
void pool_kernel(const float* __restrict__ x1, const float* __restrict__ x2,
                 const float* __restrict__ x3, const float* __restrict__ x4,
                 const int* __restrict__ batch, float* __restrict__ g, int N) {
    int gr = blockIdx.x;
    __shared__ int s_range[2];
    if (threadIdx.x == 0) {
        s_range[0] = lower_bound_i(batch, N, gr);
        s_range[1] = lower_bound_i(batch, N, gr + 1);
    }
    __syncthreads();
    int start = s_range[0], end = s_range[1];
    int tid = threadIdx.x;
    float a0 = 0.f, a1 = 0.f, a2 = 0.f, a3 = 0.f;
    for (int n = start; n < end; n++) {
        size_t off = (size_t)n * HID + tid;
        a0 += x1[off];
        a1 += x2[off];
        a2 += x3[off];
        a3 += x4[off];
    }
    float inv = 1.f / fmaxf((float)(end - start), 1.f);
    size_t go = (size_t)gr * (4 * HID);
    g[go + 0 * HID + tid] = a0 * inv;
    g[go + 1 * HID + tid] = a1 * inv;
    g[go + 2 * HID + tid] = a2 * inv;
    g[go + 3 * HID + tid] = a3 * inv;
}

// ------------- final fc4 ------------------------------------------------------
__global__ void fc4_kernel(const float* __restrict__ h, const float* __restrict__ w,
                           const float* __restrict__ b, float* __restrict__ out, int G) {
    int t = blockIdx.x * blockDim.x + threadIdx.x;
    int warp = t >> 5;
    int lane = t & 31;
    if (warp >= G) return;
    float acc = 0.f;
#pragma unroll
    for (int c = lane; c < HID; c += 32) acc += h[(size_t)warp * HID + c] * w[c];
#pragma unroll
    for (int off = 16; off; off >>= 1) acc += __shfl_xor_sync(0xFFFFFFFFu, acc, off);
    if (lane == 0) out[warp] = acc + b[0];
}

// ---------------- host orchestration ----------------------------------------
extern "C" void kernel_launch(void* const* d_in, const int* in_sizes, int n_in,
                              void* d_out, int out_size) {
    const float* x = (const float*)d_in[0];
    const int* ei = (const int*)d_in[1];
    const int* batch = (const int*)d_in[2];
    const float* W_rel[4] = {(const float*)d_in[3], (const float*)d_in[6],
                             (const float*)d_in[9], (const float*)d_in[12]};
    const float* b_rel[4] = {(const float*)d_in[4], (const float*)d_in[7],
                             (const float*)d_in[10], (const float*)d_in[13]};
    const float* W_root[4] = {(const float*)d_in[5], (const float*)d_in[8],
                              (const float*)d_in[11], (const float*)d_in[14]};
    const float* fc1_w = (const float*)d_in[15];
    const float* fc1_b = (const float*)d_in[16];
    const float* fc2_w = (const float*)d_in[17];
    const float* fc2_b = (const float*)d_in[18];
    const float* fc3_w = (const float*)d_in[19];
    const float* fc3_b = (const float*)d_in[20];
    const float* fc4_w = (const float*)d_in[21];
    const float* fc4_b = (const float*)d_in[22];
    float* out = (float*)d_out;

    int N = in_sizes[0] / NFEAT;   // 100000
    int E = in_sizes[1] / 2;       // 320000
    int G = out_size;              // 4096

    static float *agg28 = 0, *agg = 0, *x1 = 0, *x2 = 0, *x3 = 0, *x4 = 0,
                 *g = 0, *h1 = 0, *h2 = 0, *h3 = 0;
    static float *wr[3], *wo[3], *fcw1, *fcw2, *fcw3;
    static int *deg = 0, *rowptr = 0, *csr = 0, *bsum = 0, *boff = 0;
    if (!agg28) {
        cudaGetSymbolAddress((void**)&agg28, d_agg28);
        cudaGetSymbolAddress((void**)&agg, d_agg);
        cudaGetSymbolAddress((void**)&x1, d_x1);
        cudaGetSymbolAddress((void**)&x2, d_x2);
        cudaGetSymbolAddress((void**)&x3, d_x3);
        cudaGetSymbolAddress((void**)&x4, d_x4);
        cudaGetSymbolAddress((void**)&g, d_g);
        cudaGetSymbolAddress((void**)&h1, d_h1);
        cudaGetSymbolAddress((void**)&h2, d_h2);
        cudaGetSymbolAddress((void**)&h3, d_h3);
        cudaGetSymbolAddress((void**)&wr[0], d_wr2);
        cudaGetSymbolAddress((void**)&wo[0], d_wo2);
        cudaGetSymbolAddress((void**)&wr[1], d_wr3);
        cudaGetSymbolAddress((void**)&wo[1], d_wo3);
        cudaGetSymbolAddress((void**)&wr[2], d_wr4);
        cudaGetSymbolAddress((void**)&wo[2], d_wo4);
        cudaGetSymbolAddress((void**)&fcw1, d_fc1w);
        cudaGetSymbolAddress((void**)&fcw2, d_fc2w);
        cudaGetSymbolAddress((void**)&fcw3, d_fc3w);
        cudaGetSymbolAddress((void**)&deg, d_deg);
        cudaGetSymbolAddress((void**)&rowptr, d_rowptr);
        cudaGetSymbolAddress((void**)&csr, d_csr);
        cudaGetSymbolAddress((void**)&bsum, d_bsum);
        cudaGetSymbolAddress((void**)&boff, d_boff);
        cudaFuncSetAttribute(gemm_tf32_dual<true>,
                             cudaFuncAttributeMaxDynamicSharedMemorySize,
                             GEMM_SMEM_BYTES);
        cudaFuncSetAttribute(gemm_tf32_dual<false>,
                             cudaFuncAttributeMaxDynamicSharedMemorySize,
                             GEMM_SMEM_BYTES);
    }

    float* xs[4] = {x1, x2, x3, x4};

    // ---- pre-round weights to tf32 (one launch) ----
    {
        WPack p;
        int n = HID * HID;
        p.seg[0] = {W_rel[1], wr[0], n};
        p.seg[1] = {W_root[1], wo[0], n};
        p.seg[2] = {W_rel[2], wr[1], n};
        p.seg[3] = {W_root[2], wo[1], n};
        p.seg[4] = {W_rel[3], wr[2], n};
        p.seg[5] = {W_root[3], wo[2], n};
        p.seg[6] = {fc1_w, fcw1, HID * 4 * HID};
        p.seg[7] = {fc2_w, fcw2, n};
        p.seg[8] = {fc3_w, fcw3, n};
        int total = 8 * n + HID * 4 * HID;
        round_weights_kernel<<<(total + 255) / 256, 256>>>(p, total);
    }

    // ---- build CSR (dst -> list of src) ----
    {
        zero_int<<<(N + 255) / 256, 256>>>(deg, N);
        hist_kernel<<<(E + 255) / 256, 256>>>(ei, deg, E);
        int nb = (N + 511) / 512;
        scanA_kernel<<<nb, 512>>>(deg, rowptr, bsum, N);
        scanB_kernel<<<1, 256>>>(bsum, boff, nb);
        scanC_kernel<<<(N + 255) / 256, 256>>>(rowptr, boff, N);
        cursor_init_kernel<<<(N + 255) / 256, 256>>>(rowptr, deg, N);
        fill_csr_kernel<<<(E + 255) / 256, 256>>>(ei, deg, csr, E);
    }

    // ---- layer 1: 28-dim scatter + tiny-K fused GEMM (fp32, rounded out) ----
    {
        int n4 = N * NFEAT / 4;
        zero_f4<<<(n4 + 255) / 256, 256>>>((float4*)agg28, n4);
        int tot = E * 8;
        scatter28<<<(tot + 255) / 256, 256>>>(x, ei, agg28, E);
        layer1_kernel<<<(N + 15) / 16, 256>>>(agg28, x, W_rel[0], b_rel[0], W_root[0], x1, N);
    }

    // ---- layers 2..4 : CSR aggregation + tf32 dual GEMM (no mainloop cvt) ----
    for (int l = 1; l < 4; l++) {
        const float* xin = xs[l - 1];
        float* xout = xs[l];
        agg_csr_kernel<<<(N + 3) / 4, 256>>>(xin, rowptr, csr, agg, N);
        dim3 grid(HID / GBN, (N + GBM - 1) / GBM);
        int round_out = (l < 3) ? 1 : 0;  // x2,x3 rounded; x4 full precision
        gemm_tf32_dual<false><<<grid, 256, GEMM_SMEM_BYTES>>>(
            agg, HID, wr[l - 1], HID, HID,
            xin, HID, wo[l - 1], HID, HID,
            b_rel[l], xout, N, HID, 1, round_out);
    }

    // ---- global mean pool ----
    pool_kernel<<<G, 256>>>(x1, x2, x3, x4, batch, g, N);

    // ---- MLP ----
    {
        dim3 grid(HID / GBN, (G + GBM - 1) / GBM);
        gemm_tf32_dual<true><<<grid, 256, GEMM_SMEM_BYTES>>>(
            g, 4 * HID, fcw1, 4 * HID, 4 * HID,
            (const float*)0, 0, (const float*)0, 0, 0,
            fc1_b, h1, G, HID, 1, 1);   // h1 rounded
        gemm_tf32_dual<false><<<grid, 256, GEMM_SMEM_BYTES>>>(
            h1, HID, fcw2, HID, HID,
            (const float*)0, 0, (const float*)0, 0, 0,
            fc2_b, h2, G, HID, 1, 1);   // h2 rounded
        gemm_tf32_dual<false><<<grid, 256, GEMM_SMEM_BYTES>>>(
            h2, HID, fcw3, HID, HID,
            (const float*)0, 0, (const float*)0, 0, 0,
            fc3_b, h3, G, HID, 1, 0);   // h3 full precision for fc4
        int tot = G * 32;
        fc4_kernel<<<(tot + 255) / 256, 256>>>(h3, fc4_w, fc4_b, out, G);
    }
}

// round 11
// speedup vs baseline: 1.2118x; 1.0011x over previous
#include <cuda_runtime.h>
#include <cstdint>

#define N_NODES 100000
#define N_EDGES 320000
#define N_GRAPHS 4096
#define HID 256
#define NFEAT 28

// ---------------- device scratch (zero-fill bss, no runtime alloc) ----------
__device__ float d_agg28[N_NODES * NFEAT];
__device__ float d_agg[N_NODES * HID];
__device__ float d_x1[N_NODES * HID];
__device__ float d_x2[N_NODES * HID];
__device__ float d_x3[N_NODES * HID];
__device__ float d_x4[N_NODES * HID];
__device__ float d_g[N_GRAPHS * 4 * HID];
__device__ float d_h1[N_GRAPHS * HID];
__device__ float d_h2[N_GRAPHS * HID];
__device__ float d_h3[N_GRAPHS * HID];

// CSR scratch
__device__ int d_deg[N_NODES];
__device__ int d_rowptr[N_NODES + 1];
__device__ int d_csr[N_EDGES];
__device__ int d_bsum[256];
__device__ int d_boff[256];

// tf32-pre-rounded weights
__device__ float d_wr2[HID * HID], d_wo2[HID * HID];
__device__ float d_wr3[HID * HID], d_wo3[HID * HID];
__device__ float d_wr4[HID * HID], d_wo4[HID * HID];
__device__ float d_fc1w[HID * 4 * HID];
__device__ float d_fc2w[HID * HID];
__device__ float d_fc3w[HID * HID];

// ---------------- small utility kernels --------------------------------------
__global__ void zero_f4(float4* p, int n4) {
    int i = blockIdx.x * blockDim.x + threadIdx.x;
    if (i < n4) p[i] = make_float4(0.f, 0.f, 0.f, 0.f);
}

__global__ void zero_int(int* p, int n) {
    int i = blockIdx.x * blockDim.x + threadIdx.x;
    if (i < n) p[i] = 0;
}

__device__ __forceinline__ uint32_t f2tf32(float x) {
    uint32_t u;
    asm("cvt.rna.tf32.f32 %0, %1;" : "=r"(u) : "f"(x));
    return u;
}

__device__ __forceinline__ float round_tf32(float x) {
    return __uint_as_float(f2tf32(x));
}

// merged weight rounding: 9 segments in one launch
struct WSeg { const float* src; float* dst; int n; };
struct WPack { WSeg seg[9]; };

__global__ void round_weights_kernel(WPack p, int total) {
    int i = blockIdx.x * blockDim.x + threadIdx.x;
    if (i >= total) return;
#pragma unroll
    for (int s = 0; s < 9; s++) {
        if (i < p.seg[s].n) {
            p.seg[s].dst[i] = round_tf32(p.seg[s].src[i]);
            return;
        }
        i -= p.seg[s].n;
    }
}

__device__ __forceinline__ void red_add_v4(float* p, float4 v) {
    asm volatile("red.global.add.v4.f32 [%0], {%1,%2,%3,%4};"
                 :: "l"(p), "f"(v.x), "f"(v.y), "f"(v.z), "f"(v.w)
                 : "memory");
}

// ---------------- CSR build ---------------------------------------------------
__global__ void hist_kernel(const int* __restrict__ ei, int* __restrict__ deg, int E) {
    int e = blockIdx.x * blockDim.x + threadIdx.x;
    if (e < E) atomicAdd(&deg[ei[E + e]], 1);
}

__global__ void scanA_kernel(const int* __restrict__ deg, int* __restrict__ rowptr,
                             int* __restrict__ bsum, int n) {
    __shared__ int s[512];
    int i = blockIdx.x * 512 + threadIdx.x;
    int v = (i < n) ? deg[i] : 0;
    s[threadIdx.x] = v;
    __syncthreads();
#pragma unroll
    for (int o = 1; o < 512; o <<= 1) {
        int t = (threadIdx.x >= o) ? s[threadIdx.x - o] : 0;
        __syncthreads();
        s[threadIdx.x] += t;
        __syncthreads();
    }
    if (i < n) rowptr[i + 1] = s[threadIdx.x];
    if (threadIdx.x == 511) bsum[blockIdx.x] = s[511];
}

__global__ void scanB_kernel(const int* __restrict__ bsum, int* __restrict__ boff, int nb) {
    __shared__ int s[256];
    int v = (threadIdx.x < nb) ? bsum[threadIdx.x] : 0;
    s[threadIdx.x] = v;
    __syncthreads();
#pragma unroll
    for (int o = 1; o < 256; o <<= 1) {
        int t = (threadIdx.x >= o) ? s[threadIdx.x - o] : 0;
        __syncthreads();
        s[threadIdx.x] += t;
        __syncthreads();
    }
    if (threadIdx.x < nb) boff[threadIdx.x] = s[threadIdx.x] - v;
}

__global__ void scanC_kernel(int* __restrict__ rowptr, const int* __restrict__ boff, int n) {
    int i = blockIdx.x * blockDim.x + threadIdx.x;
    if (i == 0) rowptr[0] = 0;
    if (i < n) rowptr[i + 1] += boff[i >> 9];
}

__global__ void cursor_init_kernel(const int* __restrict__ rowptr, int* __restrict__ cursor, int n) {
    int i = blockIdx.x * blockDim.x + threadIdx.x;
    if (i < n) cursor[i] = rowptr[i];
}

__global__ void fill_csr_kernel(const int* __restrict__ ei, int* __restrict__ cursor,
                                int* __restrict__ csr, int E) {
    int e = blockIdx.x * blockDim.x + threadIdx.x;
    if (e >= E) return;
    int d = ei[E + e];
    int pos = atomicAdd(&cursor[d], 1);
    csr[pos] = ei[e];
}

// atomic-free aggregation; writes tf32-rounded sums (A operand of GEMM)
__global__ __launch_bounds__(256)
void agg_csr_kernel(const float* __restrict__ x, const int* __restrict__ rowptr,
                    const int* __restrict__ csr, float* __restrict__ agg, int N) {
    int node = blockIdx.x * 4 + (threadIdx.x >> 6);
    int c = (threadIdx.x & 63) << 2;
    if (node >= N) return;
    int s0 = rowptr[node], s1 = rowptr[node + 1];
    float4 acc = make_float4(0.f, 0.f, 0.f, 0.f);
    for (int i = s0; i < s1; i++) {
        int src = __ldg(&csr[i]);
        float4 v = *(const float4*)(x + (size_t)src * HID + c);
        acc.x += v.x; acc.y += v.y; acc.z += v.z; acc.w += v.w;
    }
    acc.x = round_tf32(acc.x); acc.y = round_tf32(acc.y);
    acc.z = round_tf32(acc.z); acc.w = round_tf32(acc.w);
    *(float4*)(agg + (size_t)node * HID + c) = acc;
}

// ---------------- layer-1 path (K=28) ----------------------------------------
__global__ void scatter28(const float* __restrict__ x,
                          const int* __restrict__ ei,
                          float* __restrict__ agg, int E) {
    int t = blockIdx.x * blockDim.x + threadIdx.x;
    int e = t >> 3;
    int c = t & 7;
    if (e >= E || c >= 7) return;
    int s = ei[e];
    int d = ei[E + e];
    float4 v = *(const float4*)(x + (size_t)s * NFEAT + c * 4);
    red_add_v4(agg + (size_t)d * NFEAT + c * 4, v);
}

// output rounded to tf32 (x1 is an A operand of GEMM-2)
__global__ __launch_bounds__(256)
void layer1_kernel(const float* __restrict__ agg28, const float* __restrict__ x,
                   const float* __restrict__ W_rel, const float* __restrict__ b,
                   const float* __restrict__ W_root, float* __restrict__ out, int M) {
    __shared__ float sa[16][NFEAT];
    __shared__ float sx[16][NFEAT];
    int r0 = blockIdx.x * 16;
    for (int i = threadIdx.x; i < 16 * NFEAT; i += 256) {
        int r = i / NFEAT, c = i % NFEAT;
        int row = r0 + r;
        sa[r][c] = (row < M) ? agg28[(size_t)row * NFEAT + c] : 0.f;
        sx[r][c] = (row < M) ? x[(size_t)row * NFEAT + c] : 0.f;
    }
    __syncthreads();
    int o = threadIdx.x;
    float wr[NFEAT], wo[NFEAT];
#pragma unroll
    for (int k = 0; k < NFEAT; k++) {
        wr[k] = W_rel[o * NFEAT + k];
        wo[k] = W_root[o * NFEAT + k];
    }
    float bo = b[o];
#pragma unroll 4
    for (int r = 0; r < 16; r++) {
        int row = r0 + r;
        if (row >= M) break;
        float acc = bo;
#pragma unroll
        for (int k = 0; k < NFEAT; k++) acc += sa[r][k] * wr[k] + sx[r][k] * wo[k];
        out[(size_t)row * HID + o] = round_tf32(fmaxf(acc, 0.f));
    }
}

// =================== tf32 tensor-core dual-segment NT GEMM ===================
// CVT_A=false when A operands are pre-rounded tf32 (bit-cast fragments).
#define GBM 128
#define GBN 128
#define GBK 16
#define SSTR 20
#define STAGES 3
#define STAGE_F ((GBM + GBN) * SSTR)
#define GEMM_SMEM_BYTES (STAGES * STAGE_F * 4)

__device__ __forceinline__ void cp_async16(uint32_t dst, const void* src, int nbytes) {
    asm volatile("cp.async.cg.shared.global [%0], [%1], 16, %2;"
                 :: "r"(dst), "l"(src), "r"(nbytes) : "memory");
}

__device__ __forceinline__ void mma_tf32(float* c, const uint32_t* a, const uint32_t* b) {
    asm volatile(
        "mma.sync.aligned.m16n8k8.row.col.f32.tf32.tf32.f32 "
        "{%0,%1,%2,%3}, {%4,%5,%6,%7}, {%8,%9}, {%0,%1,%2,%3};"
        : "+f"(c[0]), "+f"(c[1]), "+f"(c[2]), "+f"(c[3])
        : "r"(a[0]), "r"(a[1]), "r"(a[2]), "r"(a[3]), "r"(b[0]), "r"(b[1]));
}

template <bool CVT_A>
__global__ __launch_bounds__(256, 2)
void gemm_tf32_dual(const float* __restrict__ A0, int lda0,
                    const float* __restrict__ B0, int ldb0, int K0,
                    const float* __restrict__ A1, int lda1,
                    const float* __restrict__ B1, int ldb1, int K1,
                    const float* __restrict__ bias, float* __restrict__ C,
                    int M, int ldc, int relu, int round_out) {
    extern __shared__ float smem[];
    float* Asm = smem;
    float* Bsm = smem + STAGES * GBM * SSTR;
    uint32_t As_base = (uint32_t)__cvta_generic_to_shared(Asm);
    uint32_t Bs_base = (uint32_t)__cvta_generic_to_shared(Bsm);

    int tid = threadIdx.x;
    int lane = tid & 31;
    int wid = tid >> 5;
    int wm = wid & 3;
    int wn = wid >> 2;
    int bm = blockIdx.y * GBM;
    int bn = blockIdx.x * GBN;

    float acc[2][8][4];
#pragma unroll
    for (int mt = 0; mt < 2; mt++)
#pragma unroll
        for (int nt = 0; nt < 8; nt++)
#pragma unroll
            for (int i = 0; i < 4; i++) acc[mt][nt][i] = 0.f;

    int nk0 = K0 / GBK;
    int nk = nk0 + K1 / GBK;

    int lr = tid >> 2;
    int lc = (tid & 3) << 2;

    auto issue_stage = [&](int s, int bufi) {
        const float* A; const float* B; int lda, ldb, ko;
        if (s < nk0) { A = A0; B = B0; lda = lda0; ldb = ldb0; ko = s * GBK; }
        else         { A = A1; B = B1; lda = lda1; ldb = ldb1; ko = (s - nk0) * GBK; }
#pragma unroll
        for (int j = 0; j < 2; j++) {
            int rr = lr + j * 64;
            int row = bm + rr;
            int okA = (row < M);
            const float* gA = A + (size_t)(okA ? row : 0) * lda + ko + lc;
            uint32_t da = As_base + (uint32_t)(bufi * (GBM * SSTR) + rr * SSTR + lc) * 4u;
            cp_async16(da, gA, okA ? 16 : 0);
            const float* gB = B + (size_t)(bn + rr) * ldb + ko + lc;
            uint32_t db = Bs_base + (uint32_t)(bufi * (GBN * SSTR) + rr * SSTR + lc) * 4u;
            cp_async16(db, gB, 16);
        }
        asm volatile("cp.async.commit_group;" ::: "memory");
    };

#pragma unroll
    for (int s = 0; s < STAGES - 1; s++) {
        if (s < nk) issue_stage(s, s);
        else asm volatile("cp.async.commit_group;" ::: "memory");
    }

    int grp = lane >> 2;
    int qid = lane & 3;
    int buf = 0;

    for (int it = 0; it < nk; ++it) {
        asm volatile("cp.async.wait_group %0;" :: "n"(STAGES - 2));
        __syncthreads();

        int nx = it + STAGES - 1;
        if (nx < nk) issue_stage(nx, (buf + STAGES - 1) % STAGES);
        else asm volatile("cp.async.commit_group;" ::: "memory");

        const float* Ab = Asm + buf * (GBM * SSTR);
        const float* Bb = Bsm + buf * (GBN * SSTR);
#pragma unroll
        for (int kk = 0; kk < GBK; kk += 8) {
            uint32_t af[2][4];
            uint32_t bfr[8][2];
#pragma unroll
            for (int mt = 0; mt < 2; mt++) {
                int r0 = wm * 32 + mt * 16 + grp;
                if (CVT_A) {
                    af[mt][0] = f2tf32(Ab[(r0    ) * SSTR + kk + qid]);
                    af[mt][1] = f2tf32(Ab[(r0 + 8) * SSTR + kk + qid]);
                    af[mt][2] = f2tf32(Ab[(r0    ) * SSTR + kk + qid + 4]);
                    af[mt][3] = f2tf32(Ab[(r0 + 8) * SSTR + kk + qid + 4]);
                } else {
                    af[mt][0] = __float_as_uint(Ab[(r0    ) * SSTR + kk + qid]);
                    af[mt][1] = __float_as_uint(Ab[(r0 + 8) * SSTR + kk + qid]);
                    af[mt][2] = __float_as_uint(Ab[(r0    ) * SSTR + kk + qid + 4]);
                    af[mt][3] = __float_as_uint(Ab[(r0 + 8) * SSTR + kk + qid + 4]);
                }
            }
#pragma unroll
            for (int nt = 0; nt < 8; nt++) {
                int n0 = wn * 64 + nt * 8 + grp;
                bfr[nt][0] = __float_as_uint(Bb[n0 * SSTR + kk + qid]);
                bfr[nt][1] = __float_as_uint(Bb[n0 * SSTR + kk + qid + 4]);
            }
#pragma unroll
            for (int mt = 0; mt < 2; mt++)
#pragma unroll
                for (int nt = 0; nt < 8; nt++) mma_tf32(acc[mt][nt], af[mt], bfr[nt]);
        }
        buf = (buf + 1) % STAGES;
    }

#pragma unroll
    for (int mt = 0; mt < 2; mt++) {
#pragma unroll
        for (int nt = 0; nt < 8; nt++) {
            int row = bm + wm * 32 + mt * 16 + grp;
            int col = bn + wn * 64 + nt * 8 + 2 * qid;
            float b0 = bias[col], b1 = bias[col + 1];
            float2 v0, v1;
            v0.x = acc[mt][nt][0] + b0; v0.y = acc[mt][nt][1] + b1;
            v1.x = acc[mt][nt][2] + b0; v1.y = acc[mt][nt][3] + b1;
            if (relu) {
                v0.x = fmaxf(v0.x, 0.f); v0.y = fmaxf(v0.y, 0.f);
                v1.x = fmaxf(v1.x, 0.f); v1.y = fmaxf(v1.y, 0.f);
            }
            if (round_out) {
                v0.x = round_tf32(v0.x); v0.y = round_tf32(v0.y);
                v1.x = round_tf32(v1.x); v1.y = round_tf32(v1.y);
            }
            if (row < M)     *(float2*)(C + (size_t)row * ldc + col) = v0;
            if (row + 8 < M) *(float2*)(C + (size_t)(row + 8) * ldc + col) = v1;
        }
    }
}

// ------------- pooling -------------------------------------------------------
__device__ __forceinline__ int lower_bound_i(const int* a, int n, int v) {
    int lo = 0, hi = n;
    while (lo < hi) {
        int mid = (lo + hi) >> 1;
        if (a[mid] < v) lo = mid + 1;
        else hi = mid;
    }
    return lo;
}

__global__ __launch_bounds__(256)
void pool_kernel(const float* __restrict__ x1, const float* __restrict__ x2,
                 const float* __restrict__ x3, const float* __restrict__ x4,
                 const int* __restrict__ batch, float* __restrict__ g, int N) {
    int gr = blockIdx.x;
    __shared__ int s_range[2];
    if (threadIdx.x == 0) {
        s_range[0] = lower_bound_i(batch, N, gr);
        s_range[1] = lower_bound_i(batch, N, gr + 1);
    }
    __syncthreads();
    int start = s_range[0], end = s_range[1];
    int tid = threadIdx.x;
    float a0 = 0.f, a1 = 0.f, a2 = 0.f, a3 = 0.f;
    for (int n = start; n < end; n++) {
        size_t off = (size_t)n * HID + tid;
        a0 += x1[off];
        a1 += x2[off];
        a2 += x3[off];
        a3 += x4[off];
    }
    float inv = 1.f / fmaxf((float)(end - start), 1.f);
    size_t go = (size_t)gr * (4 * HID);
    g[go + 0 * HID + tid] = a0 * inv;
    g[go + 1 * HID + tid] = a1 * inv;
    g[go + 2 * HID + tid] = a2 * inv;
    g[go + 3 * HID + tid] = a3 * inv;
}

// ------------- final fc4 ------------------------------------------------------
__global__ void fc4_kernel(const float* __restrict__ h, const float* __restrict__ w,
                           const float* __restrict__ b, float* __restrict__ out, int G) {
    int t = blockIdx.x * blockDim.x + threadIdx.x;
    int warp = t >> 5;
    int lane = t & 31;
    if (warp >= G) return;
    float acc = 0.f;
#pragma unroll
    for (int c = lane; c < HID; c += 32) acc += h[(size_t)warp * HID + c] * w[c];
#pragma unroll
    for (int off = 16; off; off >>= 1) acc += __shfl_xor_sync(0xFFFFFFFFu, acc, off);
    if (lane == 0) out[warp] = acc + b[0];
}

// ---------------- host orchestration ----------------------------------------
extern "C" void kernel_launch(void* const* d_in, const int* in_sizes, int n_in,
                              void* d_out, int out_size) {
    const float* x = (const float*)d_in[0];
    const int* ei = (const int*)d_in[1];
    const int* batch = (const int*)d_in[2];
    const float* W_rel[4] = {(const float*)d_in[3], (const float*)d_in[6],
                             (const float*)d_in[9], (const float*)d_in[12]};
    const float* b_rel[4] = {(const float*)d_in[4], (const float*)d_in[7],
                             (const float*)d_in[10], (const float*)d_in[13]};
    const float* W_root[4] = {(const float*)d_in[5], (const float*)d_in[8],
                              (const float*)d_in[11], (const float*)d_in[14]};
    const float* fc1_w = (const float*)d_in[15];
    const float* fc1_b = (const float*)d_in[16];
    const float* fc2_w = (const float*)d_in[17];
    const float* fc2_b = (const float*)d_in[18];
    const float* fc3_w = (const float*)d_in[19];
    const float* fc3_b = (const float*)d_in[20];
    const float* fc4_w = (const float*)d_in[21];
    const float* fc4_b = (const float*)d_in[22];
    float* out = (float*)d_out;

    int N = in_sizes[0] / NFEAT;   // 100000
    int E = in_sizes[1] / 2;       // 320000
    int G = out_size;              // 4096

    static float *agg28 = 0, *agg = 0, *x1 = 0, *x2 = 0, *x3 = 0, *x4 = 0,
                 *g = 0, *h1 = 0, *h2 = 0, *h3 = 0;
    static float *wr[3], *wo[3], *fcw1, *fcw2, *fcw3;
    static int *deg = 0, *rowptr = 0, *csr = 0, *bsum = 0, *boff = 0;
    if (!agg28) {
        cudaGetSymbolAddress((void**)&agg28, d_agg28);
        cudaGetSymbolAddress((void**)&agg, d_agg);
        cudaGetSymbolAddress((void**)&x1, d_x1);
        cudaGetSymbolAddress((void**)&x2, d_x2);
        cudaGetSymbolAddress((void**)&x3, d_x3);
        cudaGetSymbolAddress((void**)&x4, d_x4);
        cudaGetSymbolAddress((void**)&g, d_g);
        cudaGetSymbolAddress((void**)&h1, d_h1);
        cudaGetSymbolAddress((void**)&h2, d_h2);
        cudaGetSymbolAddress((void**)&h3, d_h3);
        cudaGetSymbolAddress((void**)&wr[0], d_wr2);
        cudaGetSymbolAddress((void**)&wo[0], d_wo2);
        cudaGetSymbolAddress((void**)&wr[1], d_wr3);
        cudaGetSymbolAddress((void**)&wo[1], d_wo3);
        cudaGetSymbolAddress((void**)&wr[2], d_wr4);
        cudaGetSymbolAddress((void**)&wo[2], d_wo4);
        cudaGetSymbolAddress((void**)&fcw1, d_fc1w);
        cudaGetSymbolAddress((void**)&fcw2, d_fc2w);
        cudaGetSymbolAddress((void**)&fcw3, d_fc3w);
        cudaGetSymbolAddress((void**)&deg, d_deg);
        cudaGetSymbolAddress((void**)&rowptr, d_rowptr);
        cudaGetSymbolAddress((void**)&csr, d_csr);
        cudaGetSymbolAddress((void**)&bsum, d_bsum);
        cudaGetSymbolAddress((void**)&boff, d_boff);
        cudaFuncSetAttribute(gemm_tf32_dual<true>,
                             cudaFuncAttributeMaxDynamicSharedMemorySize,
                             GEMM_SMEM_BYTES);
        cudaFuncSetAttribute(gemm_tf32_dual<false>,
                             cudaFuncAttributeMaxDynamicSharedMemorySize,
                             GEMM_SMEM_BYTES);
    }

    float* xs[4] = {x1, x2, x3, x4};

    // ---- pre-round weights to tf32 (one launch) ----
    {
        WPack p;
        int n = HID * HID;
        p.seg[0] = {W_rel[1], wr[0], n};
        p.seg[1] = {W_root[1], wo[0], n};
        p.seg[2] = {W_rel[2], wr[1], n};
        p.seg[3] = {W_root[2], wo[1], n};
        p.seg[4] = {W_rel[3], wr[2], n};
        p.seg[5] = {W_root[3], wo[2], n};
        p.seg[6] = {fc1_w, fcw1, HID * 4 * HID};
        p.seg[7] = {fc2_w, fcw2, n};
        p.seg[8] = {fc3_w, fcw3, n};
        int total = 8 * n + HID * 4 * HID;
        round_weights_kernel<<<(total + 255) / 256, 256>>>(p, total);
    }

    // ---- build CSR (dst -> list of src) ----
    {
        zero_int<<<(N + 255) / 256, 256>>>(deg, N);
        hist_kernel<<<(E + 255) / 256, 256>>>(ei, deg, E);
        int nb = (N + 511) / 512;
        scanA_kernel<<<nb, 512>>>(deg, rowptr, bsum, N);
        scanB_kernel<<<1, 256>>>(bsum, boff, nb);
        scanC_kernel<<<(N + 255) / 256, 256>>>(rowptr, boff, N);
        cursor_init_kernel<<<(N + 255) / 256, 256>>>(rowptr, deg, N);
        fill_csr_kernel<<<(E + 255) / 256, 256>>>(ei, deg, csr, E);
    }

    // ---- layer 1: 28-dim scatter + tiny-K fused GEMM (fp32, rounded out) ----
    {
        int n4 = N * NFEAT / 4;
        zero_f4<<<(n4 + 255) / 256, 256>>>((float4*)agg28, n4);
        int tot = E * 8;
        scatter28<<<(tot + 255) / 256, 256>>>(x, ei, agg28, E);
        layer1_kernel<<<(N + 15) / 16, 256>>>(agg28, x, W_rel[0], b_rel[0], W_root[0], x1, N);
    }

    // ---- layers 2..4 : CSR aggregation + tf32 dual GEMM (no mainloop cvt) ----
    for (int l = 1; l < 4; l++) {
        const float* xin = xs[l - 1];
        float* xout = xs[l];
        agg_csr_kernel<<<(N + 3) / 4, 256>>>(xin, rowptr, csr, agg, N);
        dim3 grid(HID / GBN, (N + GBM - 1) / GBM);
        int round_out = (l < 3) ? 1 : 0;  // x2,x3 rounded; x4 full precision
        gemm_tf32_dual<false><<<grid, 256, GEMM_SMEM_BYTES>>>(
            agg, HID, wr[l - 1], HID, HID,
            xin, HID, wo[l - 1], HID, HID,
            b_rel[l], xout, N, HID, 1, round_out);
    }

    // ---- global mean pool ----
    pool_kernel<<<G, 256>>>(x1, x2, x3, x4, batch, g, N);

    // ---- MLP ----
    {
        dim3 grid(HID / GBN, (G + GBM - 1) / GBM);
        gemm_tf32_dual<true><<<grid, 256, GEMM_SMEM_BYTES>>>(
            g, 4 * HID, fcw1, 4 * HID, 4 * HID,
            (const float*)0, 0, (const float*)0, 0, 0,
            fc1_b, h1, G, HID, 1, 1);   // h1 rounded
        gemm_tf32_dual<false><<<grid, 256, GEMM_SMEM_BYTES>>>(
            h1, HID, fcw2, HID, HID,
            (const float*)0, 0, (const float*)0, 0, 0,
            fc2_b, h2, G, HID, 1, 1);   // h2 rounded
        gemm_tf32_dual<false><<<grid, 256, GEMM_SMEM_BYTES>>>(
            h2, HID, fcw3, HID, HID,
            (const float*)0, 0, (const float*)0, 0, 0,
            fc3_b, h3, G, HID, 1, 0);   // h3 full precision for fc4
        int tot = G * 32;
        fc4_kernel<<<(tot + 255) / 256, 256>>>(h3, fc4_w, fc4_b, out, G);
    }
}